// round 7
// baseline (speedup 1.0000x reference)
#include <cuda_runtime.h>
#include <cstddef>

#define EDIM  1024
#define BLK   256
#define FPB   4              // features per computing block
#define YGRID (EDIM / FPB)   // 256 computing blocks
#define GRID  1184           // 148 SMs * 8 blocks -> single wave

__device__ float g_y[EDIM];          // y = W @ z + b
__device__ unsigned int g_ready;     // zero-init; reset to 0 each launch
__device__ unsigned int g_done;      // zero-init; reset to 0 each launch

// ---------------------------------------------------------------------------
// Single fused kernel.
//  Blocks [0, YGRID): compute z (fast trig, once per block) into smem, dot 4
//    W rows -> g_y, publish with threadfence + g_ready counter.
//  ALL blocks: spin until g_ready == YGRID (concurrent with ramp/compute),
//    load their float4 of y (EDIM/4 == BLK), stream 256 MB with STG.128 .cs.
//  Last block to finish resets the counters -> identical state every replay.
// ---------------------------------------------------------------------------
__global__ void __launch_bounds__(BLK, 8)
fused_kernel(const float* __restrict__ bs_theta,
             const float* __restrict__ bs_phi,
             const float* __restrict__ phases,
             const float* __restrict__ squeeze_r,
             const float* __restrict__ disp_r,
             const float* __restrict__ W,
             const float* __restrict__ bvec,
             float4* __restrict__ out, size_t n4) {
    const int tid = threadIdx.x;
    const unsigned bid = blockIdx.x;

    __shared__ float zsh[EDIM];
    __shared__ float red2[2 * FPB];

    if (bid < YGRID) {
        // ---- compute z[0..1023] into shared memory (4 wires per thread) ----
        float c0, s0, c1, s1;
        __sincosf(0.5f * bs_theta[0], &s0, &c0);
        __sincosf(0.5f * bs_phi[0],   &s1, &c1);

        #pragma unroll
        for (int kk = 0; kk < EDIM / BLK; kk++) {
            const int e = tid + BLK * kk;
            float ar = 1.f, ai = 0.f, br = 0.f, bi = 0.f;
            // rx(bs_theta)
            {
                float nar =  c0 * ar + s0 * bi;
                float nai =  c0 * ai - s0 * br;
                float nbr =  s0 * ai + c0 * br;
                float nbi = -s0 * ar + c0 * bi;
                ar = nar; ai = nai; br = nbr; bi = nbi;
            }
            // ry(bs_phi)
            {
                float nar = c1 * ar - s1 * br;
                float nai = c1 * ai - s1 * bi;
                float nbr = s1 * ar + c1 * br;
                float nbi = s1 * ai + c1 * bi;
                ar = nar; ai = nai; br = nbr; bi = nbi;
            }
            // rz(phases[e])
            {
                float cp, sp;
                __sincosf(0.5f * phases[e], &sp, &cp);
                float nar = cp * ar + sp * ai;
                float nai = cp * ai - sp * ar;
                float nbr = cp * br - sp * bi;
                float nbi = cp * bi + sp * br;
                ar = nar; ai = nai; br = nbr; bi = nbi;
            }
            // ry(squeeze_r[e])
            {
                float c, s;
                __sincosf(0.5f * squeeze_r[e], &s, &c);
                float nar = c * ar - s * br;
                float nai = c * ai - s * bi;
                float nbr = s * ar + c * br;
                float nbi = s * ai + c * bi;
                ar = nar; ai = nai; br = nbr; bi = nbi;
            }
            // rx(displacement_r[e])
            {
                float c, s;
                __sincosf(0.5f * disp_r[e], &s, &c);
                float nar =  c * ar + s * bi;
                float nai =  c * ai - s * br;
                float nbr =  s * ai + c * br;
                float nbi = -s * ar + c * bi;
                ar = nar; ai = nai; br = nbr; bi = nbi;
            }
            // rz(kerr) rotates phases only -> |amp|^2 unchanged. Dropped.
            zsh[e] = (ar * ar + ai * ai) - (br * br + bi * bi);
        }
        __syncthreads();

        // ---- dot 4 W rows with z: feature j = tid/64, 64 threads each ----
        const int j = tid >> 6;
        const int k = tid & 63;
        const int f = bid * FPB + j;
        const float4* __restrict__ wrow =
            reinterpret_cast<const float4*>(W + (size_t)f * EDIM);
        const float4* __restrict__ z4 = reinterpret_cast<const float4*>(zsh);

        float p = 0.f;
        #pragma unroll
        for (int c = 0; c < 4; c++) {
            float4 w = __ldcs(&wrow[k + 64 * c]);
            float4 z = z4[k + 64 * c];
            p += w.x * z.x + w.y * z.y + w.z * z.z + w.w * z.w;
        }
        #pragma unroll
        for (int o = 16; o > 0; o >>= 1)
            p += __shfl_down_sync(0xffffffffu, p, o);

        if ((tid & 31) == 0) red2[tid >> 5] = p;  // 8 warps -> 8 slots
        __syncthreads();
        if (k == 0) {
            g_y[f] = red2[2 * j] + red2[2 * j + 1] + bvec[f];
            __threadfence();          // publish this writer's g_y store
        }
        __syncthreads();
        if (tid == 0) atomicAdd(&g_ready, 1u);
    }

    // ---- wait for y to be complete (runs under block ramp-up) ----
    if (tid == 0) {
        while (*(volatile unsigned int*)&g_ready < (unsigned)YGRID)
            __nanosleep(64);
    }
    __syncthreads();
    __threadfence();   // order the flag observation before g_y loads

    // Each thread's broadcast value: y[4*tid .. 4*tid+3]. Bypass L1 (written
    // by other SMs this launch).
    const float4 v = __ldcg(reinterpret_cast<const float4*>(g_y) + tid);

    // ---- stream the 256 MB output: pure STG.128 .cs ----
    const size_t stride = (size_t)gridDim.x * BLK;
    size_t i = (size_t)bid * BLK + tid;
    for (; i + 7 * stride < n4; i += 8 * stride) {
        __stcs(out + i,              v);
        __stcs(out + i + stride,     v);
        __stcs(out + i + 2 * stride, v);
        __stcs(out + i + 3 * stride, v);
        __stcs(out + i + 4 * stride, v);
        __stcs(out + i + 5 * stride, v);
        __stcs(out + i + 6 * stride, v);
        __stcs(out + i + 7 * stride, v);
    }
    for (; i < n4; i += stride)
        __stcs(out + i, v);

    // ---- epilogue: last block resets counters (state identical per launch).
    // No block can still be spinning here: g_done is only incremented after a
    // block passed the spin.
    __syncthreads();
    if (tid == 0) {
        __threadfence();
        unsigned d = atomicAdd(&g_done, 1u);
        if (d == gridDim.x - 1) {
            g_ready = 0;
            g_done  = 0;
            __threadfence();
        }
    }
}

// ---------------------------------------------------------------------------
// Inputs (metadata order):
//   0: x (B,S,E) f32        -- UNUSED (output is x-independent)
//   1: bs_theta (1,) f32
//   2: bs_phi   (1,) f32
//   3: phases   (E,) f32
//   4: squeeze_r(E,) f32
//   5: displacement_r (E,) f32
//   6: kerr     (E,) f32    -- UNUSED (rz does not change |amp|^2)
//   7: W_combine (E,E) f32
//   8: b_combine (E,) f32
// Output: (B,S,E) f32
// ---------------------------------------------------------------------------
extern "C" void kernel_launch(void* const* d_in, const int* in_sizes, int n_in,
                              void* d_out, int out_size) {
    const float* bs_theta = (const float*)d_in[1];
    const float* bs_phi   = (const float*)d_in[2];
    const float* phases   = (const float*)d_in[3];
    const float* squeeze  = (const float*)d_in[4];
    const float* disp     = (const float*)d_in[5];
    const float* W        = (const float*)d_in[7];
    const float* bvec     = (const float*)d_in[8];

    const size_t n4 = (size_t)out_size / 4;   // 16,777,216 float4s
    fused_kernel<<<GRID, BLK>>>(bs_theta, bs_phi, phases, squeeze, disp,
                                W, bvec, (float4*)d_out, n4);
}

// round 8
// speedup vs baseline: 1.2044x; 1.2044x over previous
#include <cuda_runtime.h>
#include <cstddef>

#define EDIM    1024
#define BLK     256
#define SLICE   16            // floats of e-dim owned per block (64 B)
#define NSLICES (EDIM / SLICE)   // 64
#define GRID    2048
#define GROUPS  (GRID / NSLICES) // 32 token groups

// ---------------------------------------------------------------------------
// Single kernel, zero inter-block synchronization.
// Block bid: slice s = bid & 63 (e-range [16s, 16s+16)), group g = bid >> 6.
//  1) compute z[0..1023] into smem (fast trig; MUFU pipe is otherwise idle)
//  2) y_s[r] = W[16s+r,:] . z + b[16s+r]  for r = 0..15  (64 KB, mostly L2)
//  3) stream its 64 B slice to every token in its group (4 threads/token,
//     16 B each, .cs streaming stores)
// ---------------------------------------------------------------------------
__global__ void __launch_bounds__(BLK)
fused_kernel(const float* __restrict__ bs_theta,
             const float* __restrict__ bs_phi,
             const float* __restrict__ phases,
             const float* __restrict__ squeeze_r,
             const float* __restrict__ disp_r,
             const float* __restrict__ W,
             const float* __restrict__ bvec,
             float* __restrict__ out, size_t n_tokens) {
    const int tid = threadIdx.x;
    const int s   = blockIdx.x & (NSLICES - 1);
    const int g   = blockIdx.x >> 6;

    __shared__ float zsh[EDIM];
    __shared__ float ysh[SLICE];

    // ---- 1) z into smem: 4 wires per thread, fast trig intrinsics ----
    float c0, s0, c1, s1;
    __sincosf(0.5f * bs_theta[0], &s0, &c0);
    __sincosf(0.5f * bs_phi[0],   &s1, &c1);

    #pragma unroll
    for (int kk = 0; kk < EDIM / BLK; kk++) {
        const int e = tid + BLK * kk;
        float ar = 1.f, ai = 0.f, br = 0.f, bi = 0.f;
        // rx(bs_theta): a' = c*a - i*s*b ; b' = -i*s*a + c*b
        {
            float nar =  c0 * ar + s0 * bi;
            float nai =  c0 * ai - s0 * br;
            float nbr =  s0 * ai + c0 * br;
            float nbi = -s0 * ar + c0 * bi;
            ar = nar; ai = nai; br = nbr; bi = nbi;
        }
        // ry(bs_phi)
        {
            float nar = c1 * ar - s1 * br;
            float nai = c1 * ai - s1 * bi;
            float nbr = s1 * ar + c1 * br;
            float nbi = s1 * ai + c1 * bi;
            ar = nar; ai = nai; br = nbr; bi = nbi;
        }
        // rz(phases[e])
        {
            float cp, sp;
            __sincosf(0.5f * phases[e], &sp, &cp);
            float nar = cp * ar + sp * ai;
            float nai = cp * ai - sp * ar;
            float nbr = cp * br - sp * bi;
            float nbi = cp * bi + sp * br;
            ar = nar; ai = nai; br = nbr; bi = nbi;
        }
        // ry(squeeze_r[e])
        {
            float c, ss;
            __sincosf(0.5f * squeeze_r[e], &ss, &c);
            float nar = c * ar - ss * br;
            float nai = c * ai - ss * bi;
            float nbr = ss * ar + c * br;
            float nbi = ss * ai + c * bi;
            ar = nar; ai = nai; br = nbr; bi = nbi;
        }
        // rx(displacement_r[e])
        {
            float c, ss;
            __sincosf(0.5f * disp_r[e], &ss, &c);
            float nar =  c * ar + ss * bi;
            float nai =  c * ai - ss * br;
            float nbr =  ss * ai + c * br;
            float nbi = -ss * ar + c * bi;
            ar = nar; ai = nai; br = nbr; bi = nbi;
        }
        // rz(kerr) rotates phases only -> |amp|^2 unchanged. Dropped.
        zsh[e] = (ar * ar + ai * ai) - (br * br + bi * bi);
    }
    __syncthreads();

    // ---- 2) y for this slice: 16 rows, 16 threads/row ----
    {
        const int row = tid >> 4;          // 0..15
        const int lr  = tid & 15;          // lane within row
        const int f   = s * SLICE + row;
        const float4* __restrict__ wrow =
            reinterpret_cast<const float4*>(W + (size_t)f * EDIM);
        const float4* __restrict__ z4 = reinterpret_cast<const float4*>(zsh);

        float p = 0.f;
        #pragma unroll
        for (int q = 0; q < 16; q++) {
            float4 w = __ldg(&wrow[lr + 16 * q]);
            float4 z = z4[lr + 16 * q];
            p += w.x * z.x + w.y * z.y + w.z * z.z + w.w * z.w;
        }
        // reduce across the 16 lanes of this row (width-16 shuffle)
        #pragma unroll
        for (int o = 8; o > 0; o >>= 1)
            p += __shfl_down_sync(0xffffffffu, p, o, 16);
        if (lr == 0) ysh[row] = p + bvec[f];
    }
    __syncthreads();

    // ---- 3) stream this slice to all tokens in group g ----
    // 4 threads per token, 16 B each; token_in_iter = tid>>2 (64 tokens/iter).
    const int quad = tid & 3;
    const float4 v = *reinterpret_cast<const float4*>(&ysh[quad * 4]);

    const size_t tpg        = n_tokens / GROUPS;           // tokens per group
    const size_t base_token = (size_t)g * tpg;
    const size_t end_token  = base_token + tpg;

    // starting element pointer for this thread
    float* p0 = out + (base_token + (tid >> 2)) * EDIM + s * SLICE + quad * 4;
    const size_t step = (size_t)64 * EDIM;                 // 64 tokens / iter

    size_t t = base_token + (tid >> 2);
    // main loop unrolled x4 (tpg = 2048 -> 32 iters -> 8 unrolled)
    for (; t + 3 * 64 < end_token; t += 4 * 64) {
        __stcs(reinterpret_cast<float4*>(p0), v);
        __stcs(reinterpret_cast<float4*>(p0 + step), v);
        __stcs(reinterpret_cast<float4*>(p0 + 2 * step), v);
        __stcs(reinterpret_cast<float4*>(p0 + 3 * step), v);
        p0 += 4 * step;
    }
    for (; t < end_token; t += 64) {
        __stcs(reinterpret_cast<float4*>(p0), v);
        p0 += step;
    }
}

// ---------------------------------------------------------------------------
// Inputs (metadata order):
//   0: x (B,S,E) f32        -- UNUSED (output is x-independent)
//   1: bs_theta (1,) f32
//   2: bs_phi   (1,) f32
//   3: phases   (E,) f32
//   4: squeeze_r(E,) f32
//   5: displacement_r (E,) f32
//   6: kerr     (E,) f32    -- UNUSED (rz does not change |amp|^2)
//   7: W_combine (E,E) f32
//   8: b_combine (E,) f32
// Output: (B,S,E) f32, B*S = 65536 tokens
// ---------------------------------------------------------------------------
extern "C" void kernel_launch(void* const* d_in, const int* in_sizes, int n_in,
                              void* d_out, int out_size) {
    const float* bs_theta = (const float*)d_in[1];
    const float* bs_phi   = (const float*)d_in[2];
    const float* phases   = (const float*)d_in[3];
    const float* squeeze  = (const float*)d_in[4];
    const float* disp     = (const float*)d_in[5];
    const float* W        = (const float*)d_in[7];
    const float* bvec     = (const float*)d_in[8];

    const size_t n_tokens = (size_t)out_size / EDIM;   // 65536

    fused_kernel<<<GRID, BLK>>>(bs_theta, bs_phi, phases, squeeze, disp,
                                W, bvec, (float*)d_out, n_tokens);
}